// round 10
// baseline (speedup 1.0000x reference)
#include <cuda_runtime.h>
#include <cuda_bf16.h>
#include <cuda_fp16.h>

// Problem dims (fixed by setup_inputs)
#define Nn 16
#define Cc 4
#define Hh 256
#define Ww 256
#define HW  (Hh * Ww)       // 65536
#define CHW (Cc * HW)       // 262144
#define INFV 1.0e10f
#define NBLK 1024           // fused-pass blocks (4 rows each)

// Scratch (device globals: no allocation allowed)
__device__ float2 g_part[NBLK];         // per-block (num, den) partials
__device__ unsigned int g_ctr;          // last-block counter (wraps via atomicInc)

__device__ __forceinline__ __half2 U2H(unsigned int u) { return *reinterpret_cast<__half2*>(&u); }
__device__ __forceinline__ unsigned int H2U(__half2 h)  { return *reinterpret_cast<unsigned int*>(&h); }

// ---------------------------------------------------------------------------
// Cold-path helpers: recompute f1 (C-direction transform) straight from target.
__device__ float f1_at_t(const int* __restrict__ tgt, int n, int c, int h, int w) {
    int base = n * CHW + (h << 8) + w;
    float m = INFV;
    if (tgt[base          ] != 0) m = fminf(m, (float)( c      *  c     ));
    if (tgt[base +     HW ] != 0) m = fminf(m, (float)((c - 1) * (c - 1)));
    if (tgt[base + 2 * HW ] != 0) m = fminf(m, (float)((c - 2) * (c - 2)));
    if (tgt[base + 3 * HW ] != 0) m = fminf(m, (float)((c - 3) * (c - 3)));
    return m;
}

// Exact H-direction transform at one (n,c,h,w): window + rare full column scan.
__device__ float exact_f2(const int* __restrict__ tgt, int n, int c, int h, int w) {
    float m = INFV;
    int j0 = h - 3 < 0 ? 0 : h - 3;
    int j1 = h + 3 > 255 ? 255 : h + 3;
    for (int j = j0; j <= j1; j++) {
        float dj = (float)(j - h);
        m = fminf(m, fmaf(dj, dj, f1_at_t(tgt, n, c, j, w)));
    }
    if (m > 16.0f) {
        m = INFV;
        for (int j = 0; j < Hh; j++) {
            float dj = (float)(j - h);
            m = fminf(m, fmaf(dj, dj, f1_at_t(tgt, n, c, j, w)));
        }
    }
    return m;
}

// Cold: recompute one thread's whole (4-pixel x 4-class) contribution exactly.
__device__ __noinline__ void recompute_unit(const int* __restrict__ tgt, int n,
                                            int h, int w0,
                                            const float* __restrict__ pred,
                                            float& num, float& den) {
    num = 0.f; den = 0.f;
    for (int k = 0; k < 4; k++) {
        int w = w0 + k;
        float d[4], e[4];
        for (int c = 0; c < 4; c++) {
            float m = INFV;
            int j0 = w - 3 < 0 ? 0 : w - 3;
            int j1 = w + 3 > 255 ? 255 : w + 3;
            for (int j = j0; j <= j1; j++) {
                float dj = (float)(j - w);
                m = fminf(m, fmaf(dj, dj, exact_f2(tgt, n, c, h, j)));
            }
            if (m > 16.0f) {
                m = INFV;
                for (int j = 0; j < Ww; j++) {
                    float dj = (float)(j - w);
                    m = fminf(m, fmaf(dj, dj, exact_f2(tgt, n, c, h, j)));
                }
            }
            d[c] = sqrtf(m);
            e[c] = __expf(pred[n * CHW + c * HW + (h << 8) + w]);
        }
        float es = e[0] + e[1] + e[2] + e[3];
        num += (e[0] * d[0] + e[1] * d[1] + e[2] * d[2] + e[3] * d[3]) / es;
        den += d[0] + d[1] + d[2] + d[3];
    }
}

__device__ __forceinline__ float fsqrt_approx(float x) {
    float r;
    asm("sqrt.approx.f32 %0, %1;" : "=f"(r) : "f"(x));
    return r;
}

// ---------------------------------------------------------------------------
// Fully fused kernel. Block = 4 consecutive (n,h) rows, 256 threads.
// P0: compute f1 (C-transform) for the 10 rows h0-3..h0+6 x 4 classes from
//     target into smem (640 int4-quad items, 2.5/thread, coalesced).
// P1: H-direction min-plus from smem (LDS), register rolling: 10 rows -> 4.
// P2: W-direction window (PRMT half-shifts) + softmax + block reduction.
// P3: last-block final reduction (atomicInc wraps the counter to 0 for graph
//     replay determinism).
// Exactness: outside-window cost >= 16 in both H and W, so any result <= 16
// is exact; any pixel whose true value > 16 yields acc > 16 and trips the
// cold full recompute.
__global__ void __launch_bounds__(256, 6) k_fused(const float* __restrict__ pred,
                                                  const int* __restrict__ tgt,
                                                  float* __restrict__ out) {
    __shared__ uint2 s_f1[4][10][64];         // [class][row j][4-px word]
    __shared__ unsigned int s_f2[4][4][132];  // [class][row r][2 + 128 + 2] half2 words
    __shared__ float rnum[8], rden[8];
    __shared__ bool  s_last;

    const __half2 C1 = __float2half2_rn(1.0f);
    const __half2 C4 = __float2half2_rn(4.0f);
    const __half2 C9 = __float2half2_rn(9.0f);
    const unsigned int INFW = 0x5BF85BF8u;    // half2(255, 255)

    int tid = threadIdx.x;
    int n = blockIdx.x >> 6;
    int h0 = (blockIdx.x & 63) << 2;

    // s_f2 borders
    if (tid < 64) {
        int c = tid >> 4, r = (tid >> 2) & 3, b = tid & 3;
        s_f2[c][r][b < 2 ? b : 128 + b] = INFW;
    }

    // ---- P0: C-transform of 10 rows into smem ----
    for (int item = tid; item < 640; item += 256) {
        int j = item >> 6, word = item & 63;
        int row = h0 - 3 + j;
        if ((unsigned)row < 256u) {
            int base = n * CHW + (row << 8) + (word << 2);
            int4 a0 = *(const int4*)(tgt + base         );
            int4 a1 = *(const int4*)(tgt + base +     HW);
            int4 a2 = *(const int4*)(tgt + base + 2 * HW);
            int4 a3 = *(const int4*)(tgt + base + 3 * HW);
            float f0[4], f1v[4], f2v[4], f3v[4];
#pragma unroll
            for (int k = 0; k < 4; k++) {
                bool t0 = (&a0.x)[k] != 0;
                bool t1 = (&a1.x)[k] != 0;
                bool t2 = (&a2.x)[k] != 0;
                bool t3 = (&a3.x)[k] != 0;
                f0[k]  = t0 ? 0.f : (t1 ? 1.f : (t2 ? 4.f : (t3 ? 9.f : 255.f)));
                f1v[k] = t1 ? 0.f : ((t0 || t2) ? 1.f : (t3 ? 4.f : 255.f));
                f2v[k] = t2 ? 0.f : ((t1 || t3) ? 1.f : (t0 ? 4.f : 255.f));
                f3v[k] = t3 ? 0.f : (t2 ? 1.f : (t1 ? 4.f : (t0 ? 9.f : 255.f)));
            }
            s_f1[0][j][word] = make_uint2(H2U(__floats2half2_rn(f0[0],  f0[1])),
                                          H2U(__floats2half2_rn(f0[2],  f0[3])));
            s_f1[1][j][word] = make_uint2(H2U(__floats2half2_rn(f1v[0], f1v[1])),
                                          H2U(__floats2half2_rn(f1v[2], f1v[3])));
            s_f1[2][j][word] = make_uint2(H2U(__floats2half2_rn(f2v[0], f2v[1])),
                                          H2U(__floats2half2_rn(f2v[2], f2v[3])));
            s_f1[3][j][word] = make_uint2(H2U(__floats2half2_rn(f3v[0], f3v[1])),
                                          H2U(__floats2half2_rn(f3v[2], f3v[3])));
        } else {
            uint2 inf2 = make_uint2(INFW, INFW);
            s_f1[0][j][word] = inf2;
            s_f1[1][j][word] = inf2;
            s_f1[2][j][word] = inf2;
            s_f1[3][j][word] = inf2;
        }
    }
    __syncthreads();

    // ---- P1: H-direction (native half2 min-plus, register rolling) ----
    {
        int c = tid >> 6, t = tid & 63;
        uint2 v[10];
#pragma unroll
        for (int s = 0; s < 10; s++) v[s] = s_f1[c][s][t];
#pragma unroll
        for (int r = 0; r < 4; r++) {
            __half2 aA = U2H(v[r + 3].x), aB = U2H(v[r + 3].y);
            aA = __hmin2(aA, __hadd2(__hmin2(U2H(v[r + 2].x), U2H(v[r + 4].x)), C1));
            aB = __hmin2(aB, __hadd2(__hmin2(U2H(v[r + 2].y), U2H(v[r + 4].y)), C1));
            aA = __hmin2(aA, __hadd2(__hmin2(U2H(v[r + 1].x), U2H(v[r + 5].x)), C4));
            aB = __hmin2(aB, __hadd2(__hmin2(U2H(v[r + 1].y), U2H(v[r + 5].y)), C4));
            aA = __hmin2(aA, __hadd2(__hmin2(U2H(v[r    ].x), U2H(v[r + 6].x)), C9));
            aB = __hmin2(aB, __hadd2(__hmin2(U2H(v[r    ].y), U2H(v[r + 6].y)), C9));
            s_f2[c][r][2 + 2 * t    ] = H2U(aA);
            s_f2[c][r][2 + 2 * t + 1] = H2U(aB);
        }
    }
    __syncthreads();

    // ---- P2: W-direction + softmax ----
    float num, den;
    {
        int row = tid >> 6, t = tid & 63;
        int h = h0 + row, w0 = t << 2;
        int pbase = n * CHW + (h << 8) + w0;

        float se[4]  = {0.f, 0.f, 0.f, 0.f};
        float sed[4] = {0.f, 0.f, 0.f, 0.f};
        float sd[4]  = {0.f, 0.f, 0.f, 0.f};
        __half2 hmx = __float2half2_rn(0.0f);

#pragma unroll
        for (int c = 0; c < 4; c++) {
            const unsigned int* __restrict__ sb = s_f2[c][row];
            uint2 wa = *(const uint2*)(sb + 2 * t);      // logical words 2t-2, 2t-1
            uint2 wb = *(const uint2*)(sb + 2 * t + 2);  // 2t, 2t+1 (center)
            uint2 wc = *(const uint2*)(sb + 2 * t + 4);  // 2t+2, 2t+3

            unsigned int p01 = __byte_perm(wa.x, wa.y, 0x5432);
            unsigned int p12 = __byte_perm(wa.y, wb.x, 0x5432);
            unsigned int p23 = __byte_perm(wb.x, wb.y, 0x5432);
            unsigned int p34 = __byte_perm(wb.y, wc.x, 0x5432);
            unsigned int p45 = __byte_perm(wc.x, wc.y, 0x5432);

            __half2 aA = U2H(wb.x), aB = U2H(wb.y);
            aA = __hmin2(aA, __hadd2(__hmin2(U2H(p12), U2H(p23)), C1));
            aB = __hmin2(aB, __hadd2(__hmin2(U2H(p23), U2H(p34)), C1));
            aA = __hmin2(aA, __hadd2(__hmin2(U2H(wa.y), U2H(wb.y)), C4));
            aB = __hmin2(aB, __hadd2(__hmin2(U2H(wb.x), U2H(wc.x)), C4));
            aA = __hmin2(aA, __hadd2(__hmin2(U2H(p01), U2H(p34)), C9));
            aB = __hmin2(aB, __hadd2(__hmin2(U2H(p12), U2H(p45)), C9));
            hmx = __hmax2(hmx, __hmax2(aA, aB));

            float2 fA = __half22float2(aA), fB = __half22float2(aB);
            float d0 = fsqrt_approx(fA.x), d1 = fsqrt_approx(fA.y);
            float d2 = fsqrt_approx(fB.x), d3 = fsqrt_approx(fB.y);

            float4 x4 = *(const float4*)(pred + pbase + c * HW);
            float e0 = __expf(x4.x), e1 = __expf(x4.y), e2 = __expf(x4.z), e3 = __expf(x4.w);
            se[0]  += e0;      se[1]  += e1;      se[2]  += e2;      se[3]  += e3;
            sed[0] += e0 * d0; sed[1] += e1 * d1; sed[2] += e2 * d2; sed[3] += e3 * d3;
            sd[0]  += d0;      sd[1]  += d1;      sd[2]  += d2;      sd[3]  += d3;
        }

        num = __fdividef(sed[0], se[0]) + __fdividef(sed[1], se[1]) +
              __fdividef(sed[2], se[2]) + __fdividef(sed[3], se[3]);
        den = sd[0] + sd[1] + sd[2] + sd[3];

        float chk = fmaxf(__half2float(__low2half(hmx)), __half2float(__high2half(hmx)));
        if (chk > 16.0f)     // astronomically cold: redo this unit exactly
            recompute_unit(tgt, n, h, w0, pred, num, den);
    }

    // ---- block reduce ----
#pragma unroll
    for (int o = 16; o; o >>= 1) {
        num += __shfl_xor_sync(0xFFFFFFFFu, num, o);
        den += __shfl_xor_sync(0xFFFFFFFFu, den, o);
    }
    int lane = tid & 31, wid = tid >> 5;
    if (lane == 0) { rnum[wid] = num; rden[wid] = den; }
    __syncthreads();
    if (wid == 0) {
        num = (lane < 8) ? rnum[lane] : 0.f;
        den = (lane < 8) ? rden[lane] : 0.f;
#pragma unroll
        for (int o = 4; o; o >>= 1) {
            num += __shfl_xor_sync(0xFFFFFFFFu, num, o);
            den += __shfl_xor_sync(0xFFFFFFFFu, den, o);
        }
        if (lane == 0) g_part[blockIdx.x] = make_float2(num, den);
    }

    // ---- P3: last-block final reduction (self-resetting counter) ----
    __threadfence();
    if (threadIdx.x == 0) {
        unsigned int prevc = atomicInc(&g_ctr, NBLK - 1);  // wraps to 0 on last
        s_last = (prevc == (unsigned int)(NBLK - 1));
    }
    __syncthreads();
    if (!s_last) return;

    __shared__ double snum[8], sden[8];
    double dn = 0.0, dd = 0.0;
#pragma unroll
    for (int q = 0; q < NBLK / 256; q++) {
        float2 p = g_part[q * 256 + tid];
        dn += (double)p.x;
        dd += (double)p.y;
    }
#pragma unroll
    for (int o = 16; o; o >>= 1) {
        dn += __shfl_xor_sync(0xFFFFFFFFu, dn, o);
        dd += __shfl_xor_sync(0xFFFFFFFFu, dd, o);
    }
    if (lane == 0) { snum[wid] = dn; sden[wid] = dd; }
    __syncthreads();
    if (wid == 0) {
        dn = (lane < 8) ? snum[lane] : 0.0;
        dd = (lane < 8) ? sden[lane] : 0.0;
#pragma unroll
        for (int o = 4; o; o >>= 1) {
            dn += __shfl_xor_sync(0xFFFFFFFFu, dn, o);
            dd += __shfl_xor_sync(0xFFFFFFFFu, dd, o);
        }
        if (lane == 0) out[0] = (float)(dn / (dd + 1e-10));
    }
}

// ---------------------------------------------------------------------------
extern "C" void kernel_launch(void* const* d_in, const int* in_sizes, int n_in,
                              void* d_out, int out_size) {
    const float* pred = (const float*)d_in[0];
    const int*   tgt  = (const int*)d_in[1];
    float*       out  = (float*)d_out;

    k_fused<<<NBLK, 256>>>(pred, tgt, out);
}

// round 11
// speedup vs baseline: 1.0370x; 1.0370x over previous
#include <cuda_runtime.h>
#include <cuda_bf16.h>
#include <cuda_fp16.h>

// Problem dims (fixed by setup_inputs)
#define Nn 16
#define Cc 4
#define Hh 256
#define Ww 256
#define HW  (Hh * Ww)       // 65536
#define CHW (Cc * HW)       // 262144
#define TOT (Nn * CHW)      // 4194304
#define INFV 1.0e10f
#define NBLK 512            // main-pass blocks (8 rows each)

// Scratch (device globals: no allocation allowed)
__device__ __half g_f1h[TOT];           // after C pass: {0,1,4,9, 255=INF} as half
__device__ float2 g_part[NBLK];         // per-block (num, den) partials
__device__ unsigned int g_ctr;          // last-block counter (self-wrapping)

__device__ __forceinline__ __half2 U2H(unsigned int u) { return *reinterpret_cast<__half2*>(&u); }
__device__ __forceinline__ unsigned int H2U(__half2 h)  { return *reinterpret_cast<unsigned int*>(&h); }

// ---------------------------------------------------------------------------
// C pass: f1[c] = min_{c'} (c-c')^2 + (t[c']!=0 ? 0 : INF), written as half.
__global__ void k_cpass(const int* __restrict__ tgt) {
    int idx = blockIdx.x * blockDim.x + threadIdx.x;   // over N*H*W/8 = 131072
    int n   = idx >> 13;
    int rem = idx & 8191;
    int base = n * CHW + (rem << 3);

    int4 a0a = *(const int4*)(tgt + base          ), a0b = *(const int4*)(tgt + base           + 4);
    int4 a1a = *(const int4*)(tgt + base +     HW ), a1b = *(const int4*)(tgt + base +     HW  + 4);
    int4 a2a = *(const int4*)(tgt + base + 2 * HW ), a2b = *(const int4*)(tgt + base + 2 * HW  + 4);
    int4 a3a = *(const int4*)(tgt + base + 3 * HW ), a3b = *(const int4*)(tgt + base + 3 * HW  + 4);

    float f0[8], f1[8], f2[8], f3[8];
#pragma unroll
    for (int k = 0; k < 8; k++) {
        bool t0 = ((k < 4) ? (&a0a.x)[k] : (&a0b.x)[k - 4]) != 0;
        bool t1 = ((k < 4) ? (&a1a.x)[k] : (&a1b.x)[k - 4]) != 0;
        bool t2 = ((k < 4) ? (&a2a.x)[k] : (&a2b.x)[k - 4]) != 0;
        bool t3 = ((k < 4) ? (&a3a.x)[k] : (&a3b.x)[k - 4]) != 0;
        f0[k] = t0 ? 0.f : (t1 ? 1.f : (t2 ? 4.f : (t3 ? 9.f : 255.f)));
        f1[k] = t1 ? 0.f : ((t0 || t2) ? 1.f : (t3 ? 4.f : 255.f));
        f2[k] = t2 ? 0.f : ((t1 || t3) ? 1.f : (t0 ? 4.f : 255.f));
        f3[k] = t3 ? 0.f : (t2 ? 1.f : (t1 ? 4.f : (t0 ? 9.f : 255.f)));
    }
    uint4 o;
    o = make_uint4(H2U(__floats2half2_rn(f0[0], f0[1])), H2U(__floats2half2_rn(f0[2], f0[3])),
                   H2U(__floats2half2_rn(f0[4], f0[5])), H2U(__floats2half2_rn(f0[6], f0[7])));
    *(uint4*)(g_f1h + base         ) = o;
    o = make_uint4(H2U(__floats2half2_rn(f1[0], f1[1])), H2U(__floats2half2_rn(f1[2], f1[3])),
                   H2U(__floats2half2_rn(f1[4], f1[5])), H2U(__floats2half2_rn(f1[6], f1[7])));
    *(uint4*)(g_f1h + base +     HW) = o;
    o = make_uint4(H2U(__floats2half2_rn(f2[0], f2[1])), H2U(__floats2half2_rn(f2[2], f2[3])),
                   H2U(__floats2half2_rn(f2[4], f2[5])), H2U(__floats2half2_rn(f2[6], f2[7])));
    *(uint4*)(g_f1h + base + 2 * HW) = o;
    o = make_uint4(H2U(__floats2half2_rn(f3[0], f3[1])), H2U(__floats2half2_rn(f3[2], f3[3])),
                   H2U(__floats2half2_rn(f3[4], f3[5])), H2U(__floats2half2_rn(f3[6], f3[7])));
    *(uint4*)(g_f1h + base + 3 * HW) = o;
}

// ---------------------------------------------------------------------------
__device__ __forceinline__ float f1_at(int n, int c, int h, int w) {
    float v = __half2float(g_f1h[((n * Cc + c) << 16) + (h << 8) + w]);
    return (v >= 255.f) ? INFV : v;
}

// Exact H-direction transform at one (n,c,h,w): window + rare full column scan.
__device__ float exact_f2(int n, int c, int h, int w) {
    float m = INFV;
    int j0 = h - 3 < 0 ? 0 : h - 3;
    int j1 = h + 3 > 255 ? 255 : h + 3;
    for (int j = j0; j <= j1; j++) {
        float dj = (float)(j - h);
        m = fminf(m, fmaf(dj, dj, f1_at(n, c, j, w)));
    }
    if (m > 16.0f) {
        m = INFV;
        for (int j = 0; j < Hh; j++) {
            float dj = (float)(j - h);
            m = fminf(m, fmaf(dj, dj, f1_at(n, c, j, w)));
        }
    }
    return m;
}

// Cold: recompute one thread's whole (8-pixel x 4-class) contribution exactly.
__device__ __noinline__ void recompute_unit(int n, int h, int w0,
                                            const float* __restrict__ pred,
                                            float& num, float& den) {
    num = 0.f; den = 0.f;
    for (int k = 0; k < 8; k++) {
        int w = w0 + k;
        float d[4], e[4];
        for (int c = 0; c < 4; c++) {
            float m = INFV;
            int j0 = w - 3 < 0 ? 0 : w - 3;
            int j1 = w + 3 > 255 ? 255 : w + 3;
            for (int j = j0; j <= j1; j++) {
                float dj = (float)(j - w);
                m = fminf(m, fmaf(dj, dj, exact_f2(n, c, h, j)));
            }
            if (m > 16.0f) {
                m = INFV;
                for (int j = 0; j < Ww; j++) {
                    float dj = (float)(j - w);
                    m = fminf(m, fmaf(dj, dj, exact_f2(n, c, h, j)));
                }
            }
            d[c] = sqrtf(m);
            e[c] = __expf(pred[n * CHW + c * HW + (h << 8) + w]);
        }
        float es = e[0] + e[1] + e[2] + e[3];
        num += (e[0] * d[0] + e[1] * d[1] + e[2] * d[2] + e[3] * d[3]) / es;
        den += d[0] + d[1] + d[2] + d[3];
    }
}

__device__ __forceinline__ float fsqrt_approx(float x) {
    float r;
    asm("sqrt.approx.f32 %0, %1;" : "=f"(r) : "f"(x));
    return r;
}

// ---------------------------------------------------------------------------
// Main pass. Block = 8 consecutive (n,h) rows, 256 threads, <=1 wave.
// P1: thread = (class, 4-px column); rolls 14 half2-pair rows (h0-3..h0+10)
//     through registers -> 8 H-pass word-pairs into padded smem.
// P2: warp = one row; thread = 8 px. W window from smem via PRMT half-shifts
//     (7 perms per class), softmax, block reduce. One cold check per thread.
// Exactness: outside-window cost >= 16 in both H and W => any result <= 16
// is exact; any pixel whose true value > 16 trips the cold recompute.
__global__ void __launch_bounds__(256, 4) k_main(const float* __restrict__ pred,
                                                 float* __restrict__ out) {
    __shared__ unsigned int s_f2[4][8][132];  // [class][row][2 + 128 + 2] half2 words
    __shared__ float rnum[8], rden[8];
    __shared__ bool  s_last;

    const __half2 C1 = __float2half2_rn(1.0f);
    const __half2 C4 = __float2half2_rn(4.0f);
    const __half2 C9 = __float2half2_rn(9.0f);
    const unsigned int INFW = 0x5BF85BF8u;    // half2(255, 255)

    int tid = threadIdx.x;
    int n = blockIdx.x >> 5;
    int h0 = (blockIdx.x & 31) << 3;

    // s_f2 borders: 4c x 8r x 4 pad words = 128 items
    if (tid < 128) {
        int c = tid >> 5, r = (tid >> 2) & 7, b = tid & 3;
        s_f2[c][r][b < 2 ? b : 128 + b] = INFW;
    }

    // ---- P1: H-direction (native half2 min-plus, 14 -> 8 register rolling) ----
    {
        int c = tid >> 6, t = tid & 63;
        const __half* __restrict__ pc = g_f1h + ((n * Cc + c) << 16) + (t << 2);
        uint2 v[14];
#pragma unroll
        for (int s = 0; s < 14; s++) {
            int j = h0 - 3 + s;
            v[s] = ((unsigned)j < 256u) ? *(const uint2*)(pc + (j << 8))
                                        : make_uint2(INFW, INFW);
        }
#pragma unroll
        for (int r = 0; r < 8; r++) {
            __half2 aA = U2H(v[r + 3].x), aB = U2H(v[r + 3].y);
            aA = __hmin2(aA, __hadd2(__hmin2(U2H(v[r + 2].x), U2H(v[r + 4].x)), C1));
            aB = __hmin2(aB, __hadd2(__hmin2(U2H(v[r + 2].y), U2H(v[r + 4].y)), C1));
            aA = __hmin2(aA, __hadd2(__hmin2(U2H(v[r + 1].x), U2H(v[r + 5].x)), C4));
            aB = __hmin2(aB, __hadd2(__hmin2(U2H(v[r + 1].y), U2H(v[r + 5].y)), C4));
            aA = __hmin2(aA, __hadd2(__hmin2(U2H(v[r    ].x), U2H(v[r + 6].x)), C9));
            aB = __hmin2(aB, __hadd2(__hmin2(U2H(v[r    ].y), U2H(v[r + 6].y)), C9));
            *(uint2*)&s_f2[c][r][2 + 2 * t] = make_uint2(H2U(aA), H2U(aB));
        }
    }
    __syncthreads();

    // ---- P2: W-direction + softmax, 8 px per thread ----
    float num, den;
    {
        int row = tid >> 5, t = tid & 31;
        int h = h0 + row, w0 = t << 3;
        int pbase = n * CHW + (h << 8) + w0;

        float se[8]  = {0.f,0.f,0.f,0.f,0.f,0.f,0.f,0.f};
        float sed[8] = {0.f,0.f,0.f,0.f,0.f,0.f,0.f,0.f};
        den = 0.f;
        __half2 hmx = __float2half2_rn(0.0f);

#pragma unroll
        for (int c = 0; c < 4; c++) {
            const unsigned int* __restrict__ sb = s_f2[c][row];
            uint2 wa = *(const uint2*)(sb + 4 * t);      // logical words 4t-2, 4t-1
            uint2 wb = *(const uint2*)(sb + 4 * t + 2);  // 4t,   4t+1 (center)
            uint2 wc = *(const uint2*)(sb + 4 * t + 4);  // 4t+2, 4t+3 (center)
            uint2 wd = *(const uint2*)(sb + 4 * t + 6);  // 4t+4, 4t+5

            unsigned int m2 = wa.x, m1 = wa.y;
            unsigned int c0 = wb.x, c1 = wb.y, c2 = wc.x, c3 = wc.y;
            unsigned int p1 = wd.x, p2 = wd.y;

            unsigned int Pm1 = __byte_perm(m2, m1, 0x5432);
            unsigned int P0  = __byte_perm(m1, c0, 0x5432);
            unsigned int P1  = __byte_perm(c0, c1, 0x5432);
            unsigned int P2  = __byte_perm(c1, c2, 0x5432);
            unsigned int P3  = __byte_perm(c2, c3, 0x5432);
            unsigned int P4  = __byte_perm(c3, p1, 0x5432);
            unsigned int P5  = __byte_perm(p1, p2, 0x5432);

            __half2 a0 = U2H(c0), a1 = U2H(c1), a2 = U2H(c2), a3 = U2H(c3);
            a0 = __hmin2(a0, __hadd2(__hmin2(U2H(P0),  U2H(P1)), C1));
            a1 = __hmin2(a1, __hadd2(__hmin2(U2H(P1),  U2H(P2)), C1));
            a2 = __hmin2(a2, __hadd2(__hmin2(U2H(P2),  U2H(P3)), C1));
            a3 = __hmin2(a3, __hadd2(__hmin2(U2H(P3),  U2H(P4)), C1));
            a0 = __hmin2(a0, __hadd2(__hmin2(U2H(m1),  U2H(c1)), C4));
            a1 = __hmin2(a1, __hadd2(__hmin2(U2H(c0),  U2H(c2)), C4));
            a2 = __hmin2(a2, __hadd2(__hmin2(U2H(c1),  U2H(c3)), C4));
            a3 = __hmin2(a3, __hadd2(__hmin2(U2H(c2),  U2H(p1)), C4));
            a0 = __hmin2(a0, __hadd2(__hmin2(U2H(Pm1), U2H(P2)), C9));
            a1 = __hmin2(a1, __hadd2(__hmin2(U2H(P0),  U2H(P3)), C9));
            a2 = __hmin2(a2, __hadd2(__hmin2(U2H(P1),  U2H(P4)), C9));
            a3 = __hmin2(a3, __hadd2(__hmin2(U2H(P2),  U2H(P5)), C9));

            hmx = __hmax2(hmx, __hmax2(__hmax2(a0, a1), __hmax2(a2, a3)));

            float2 fA = __half22float2(a0), fB = __half22float2(a1);
            float2 fC = __half22float2(a2), fD = __half22float2(a3);
            float d0 = fsqrt_approx(fA.x), d1 = fsqrt_approx(fA.y);
            float d2 = fsqrt_approx(fB.x), d3 = fsqrt_approx(fB.y);
            float d4 = fsqrt_approx(fC.x), d5 = fsqrt_approx(fC.y);
            float d6 = fsqrt_approx(fD.x), d7 = fsqrt_approx(fD.y);

            float4 xa = *(const float4*)(pred + pbase + c * HW);
            float4 xb = *(const float4*)(pred + pbase + c * HW + 4);
            float e0 = __expf(xa.x), e1 = __expf(xa.y), e2 = __expf(xa.z), e3 = __expf(xa.w);
            float e4 = __expf(xb.x), e5 = __expf(xb.y), e6 = __expf(xb.z), e7 = __expf(xb.w);
            se[0] += e0; se[1] += e1; se[2] += e2; se[3] += e3;
            se[4] += e4; se[5] += e5; se[6] += e6; se[7] += e7;
            sed[0] += e0 * d0; sed[1] += e1 * d1; sed[2] += e2 * d2; sed[3] += e3 * d3;
            sed[4] += e4 * d4; sed[5] += e5 * d5; sed[6] += e6 * d6; sed[7] += e7 * d7;
            den += (d0 + d1) + (d2 + d3) + (d4 + d5) + (d6 + d7);
        }

        num = __fdividef(sed[0], se[0]) + __fdividef(sed[1], se[1]) +
              __fdividef(sed[2], se[2]) + __fdividef(sed[3], se[3]) +
              __fdividef(sed[4], se[4]) + __fdividef(sed[5], se[5]) +
              __fdividef(sed[6], se[6]) + __fdividef(sed[7], se[7]);

        float chk = fmaxf(__half2float(__low2half(hmx)), __half2float(__high2half(hmx)));
        if (chk > 16.0f)     // astronomically cold: redo this unit exactly
            recompute_unit(n, h, w0, pred, num, den);
    }

    // ---- block reduce ----
#pragma unroll
    for (int o = 16; o; o >>= 1) {
        num += __shfl_xor_sync(0xFFFFFFFFu, num, o);
        den += __shfl_xor_sync(0xFFFFFFFFu, den, o);
    }
    int lane = tid & 31, wid = tid >> 5;
    if (lane == 0) { rnum[wid] = num; rden[wid] = den; }
    __syncthreads();
    if (wid == 0) {
        num = (lane < 8) ? rnum[lane] : 0.f;
        den = (lane < 8) ? rden[lane] : 0.f;
#pragma unroll
        for (int o = 4; o; o >>= 1) {
            num += __shfl_xor_sync(0xFFFFFFFFu, num, o);
            den += __shfl_xor_sync(0xFFFFFFFFu, den, o);
        }
        if (lane == 0) g_part[blockIdx.x] = make_float2(num, den);
    }

    // ---- last-block final reduction (self-resetting counter) ----
    __threadfence();
    if (threadIdx.x == 0) {
        unsigned int prevc = atomicInc(&g_ctr, NBLK - 1);  // wraps to 0 on last
        s_last = (prevc == (unsigned int)(NBLK - 1));
    }
    __syncthreads();
    if (!s_last) return;

    __shared__ double snum[8], sden[8];
    double dn = 0.0, dd = 0.0;
#pragma unroll
    for (int q = 0; q < NBLK / 256; q++) {
        float2 p = g_part[q * 256 + tid];
        dn += (double)p.x;
        dd += (double)p.y;
    }
#pragma unroll
    for (int o = 16; o; o >>= 1) {
        dn += __shfl_xor_sync(0xFFFFFFFFu, dn, o);
        dd += __shfl_xor_sync(0xFFFFFFFFu, dd, o);
    }
    if (lane == 0) { snum[wid] = dn; sden[wid] = dd; }
    __syncthreads();
    if (wid == 0) {
        dn = (lane < 8) ? snum[lane] : 0.0;
        dd = (lane < 8) ? sden[lane] : 0.0;
#pragma unroll
        for (int o = 4; o; o >>= 1) {
            dn += __shfl_xor_sync(0xFFFFFFFFu, dn, o);
            dd += __shfl_xor_sync(0xFFFFFFFFu, dd, o);
        }
        if (lane == 0) out[0] = (float)(dn / (dd + 1e-10));
    }
}

// ---------------------------------------------------------------------------
extern "C" void kernel_launch(void* const* d_in, const int* in_sizes, int n_in,
                              void* d_out, int out_size) {
    const float* pred = (const float*)d_in[0];
    const int*   tgt  = (const int*)d_in[1];
    float*       out  = (float*)d_out;

    k_cpass<<<(Nn * HW / 8) / 256, 256>>>(tgt);
    k_main<<<NBLK, 256>>>(pred, out);
}

// round 13
// speedup vs baseline: 1.4867x; 1.4337x over previous
#include <cuda_runtime.h>
#include <cuda_bf16.h>
#include <cuda_fp16.h>

// Problem dims (fixed by setup_inputs)
#define Nn 16
#define Cc 4
#define Hh 256
#define Ww 256
#define HW  (Hh * Ww)       // 65536
#define CHW (Cc * HW)       // 262144
#define INFV 1.0e10f
#define NBLK 1024           // main-pass blocks (4 rows each)
// Padded f1 plane: 4 guard rows (INF) above and below the 256 real rows.
#define PROWS 264
#define PSTRIDE (PROWS * 256)   // 67584 half elements per (n,c) plane

// Scratch (device globals: no allocation allowed)
__device__ __half g_f1h[Nn * Cc * PSTRIDE];  // padded C-pass output
__device__ float2 g_part[NBLK];              // per-block (num, den) partials
__device__ unsigned int g_ctr;               // last-block counter (self-wrapping)

__device__ __forceinline__ __half2 U2H(unsigned int u) { return *reinterpret_cast<__half2*>(&u); }
__device__ __forceinline__ unsigned int H2U(__half2 h)  { return *reinterpret_cast<unsigned int*>(&h); }

// ---------------------------------------------------------------------------
// C pass: f1[c] = min_{c'} (c-c')^2 + (t[c']!=0 ? 0 : INF), half, padded rows.
// First 16384 threads also fill the 8 guard rows per plane with INF.
__global__ void k_cpass(const int* __restrict__ tgt) {
    int idx = blockIdx.x * blockDim.x + threadIdx.x;   // over N*H*W/8 = 131072
    const unsigned int INFW = 0x5BF85BF8u;             // half2(255,255)

    if (idx < 16384) {   // pad fill: 64 planes x 8 rows x 256 half / 8 per uint4
        int plane = idx >> 8;
        int r8    = (idx >> 5) & 7;
        int word8 = idx & 31;
        int row   = (r8 < 4) ? r8 : 256 + r8;
        *(uint4*)(g_f1h + plane * PSTRIDE + (row << 8) + (word8 << 3)) =
            make_uint4(INFW, INFW, INFW, INFW);
    }

    int n   = idx >> 13;
    int rem = idx & 8191;
    int hw  = rem << 3;
    int row = hw >> 8, col = hw & 255;
    int base = n * CHW + hw;

    int4 a0a = *(const int4*)(tgt + base          ), a0b = *(const int4*)(tgt + base           + 4);
    int4 a1a = *(const int4*)(tgt + base +     HW ), a1b = *(const int4*)(tgt + base +     HW  + 4);
    int4 a2a = *(const int4*)(tgt + base + 2 * HW ), a2b = *(const int4*)(tgt + base + 2 * HW  + 4);
    int4 a3a = *(const int4*)(tgt + base + 3 * HW ), a3b = *(const int4*)(tgt + base + 3 * HW  + 4);

    float f0[8], f1[8], f2[8], f3[8];
#pragma unroll
    for (int k = 0; k < 8; k++) {
        bool t0 = ((k < 4) ? (&a0a.x)[k] : (&a0b.x)[k - 4]) != 0;
        bool t1 = ((k < 4) ? (&a1a.x)[k] : (&a1b.x)[k - 4]) != 0;
        bool t2 = ((k < 4) ? (&a2a.x)[k] : (&a2b.x)[k - 4]) != 0;
        bool t3 = ((k < 4) ? (&a3a.x)[k] : (&a3b.x)[k - 4]) != 0;
        f0[k] = t0 ? 0.f : (t1 ? 1.f : (t2 ? 4.f : (t3 ? 9.f : 255.f)));
        f1[k] = t1 ? 0.f : ((t0 || t2) ? 1.f : (t3 ? 4.f : 255.f));
        f2[k] = t2 ? 0.f : ((t1 || t3) ? 1.f : (t0 ? 4.f : 255.f));
        f3[k] = t3 ? 0.f : (t2 ? 1.f : (t1 ? 4.f : (t0 ? 9.f : 255.f)));
    }
    int obase = (n * Cc) * PSTRIDE + ((row + 4) << 8) + col;
    uint4 o;
    o = make_uint4(H2U(__floats2half2_rn(f0[0], f0[1])), H2U(__floats2half2_rn(f0[2], f0[3])),
                   H2U(__floats2half2_rn(f0[4], f0[5])), H2U(__floats2half2_rn(f0[6], f0[7])));
    *(uint4*)(g_f1h + obase              ) = o;
    o = make_uint4(H2U(__floats2half2_rn(f1[0], f1[1])), H2U(__floats2half2_rn(f1[2], f1[3])),
                   H2U(__floats2half2_rn(f1[4], f1[5])), H2U(__floats2half2_rn(f1[6], f1[7])));
    *(uint4*)(g_f1h + obase +     PSTRIDE) = o;
    o = make_uint4(H2U(__floats2half2_rn(f2[0], f2[1])), H2U(__floats2half2_rn(f2[2], f2[3])),
                   H2U(__floats2half2_rn(f2[4], f2[5])), H2U(__floats2half2_rn(f2[6], f2[7])));
    *(uint4*)(g_f1h + obase + 2 * PSTRIDE) = o;
    o = make_uint4(H2U(__floats2half2_rn(f3[0], f3[1])), H2U(__floats2half2_rn(f3[2], f3[3])),
                   H2U(__floats2half2_rn(f3[4], f3[5])), H2U(__floats2half2_rn(f3[6], f3[7])));
    *(uint4*)(g_f1h + obase + 3 * PSTRIDE) = o;
}

// ---------------------------------------------------------------------------
__device__ __forceinline__ float f1_at(int n, int c, int h, int w) {
    float v = __half2float(g_f1h[(n * Cc + c) * PSTRIDE + ((h + 4) << 8) + w]);
    return (v >= 255.f) ? INFV : v;
}

// Exact H-direction transform at one (n,c,h,w): window + rare full column scan.
__device__ float exact_f2(int n, int c, int h, int w) {
    float m = INFV;
    int j0 = h - 3 < 0 ? 0 : h - 3;
    int j1 = h + 3 > 255 ? 255 : h + 3;
    for (int j = j0; j <= j1; j++) {
        float dj = (float)(j - h);
        m = fminf(m, fmaf(dj, dj, f1_at(n, c, j, w)));
    }
    if (m > 16.0f) {
        m = INFV;
        for (int j = 0; j < Hh; j++) {
            float dj = (float)(j - h);
            m = fminf(m, fmaf(dj, dj, f1_at(n, c, j, w)));
        }
    }
    return m;
}

// Cold: recompute one thread's whole (4-pixel x 4-class) contribution exactly.
__device__ __noinline__ void recompute_unit(int n, int h, int w0,
                                            const float* __restrict__ pred,
                                            float& num, float& den) {
    num = 0.f; den = 0.f;
    for (int k = 0; k < 4; k++) {
        int w = w0 + k;
        float d[4], e[4];
        for (int c = 0; c < 4; c++) {
            float m = INFV;
            int j0 = w - 3 < 0 ? 0 : w - 3;
            int j1 = w + 3 > 255 ? 255 : w + 3;
            for (int j = j0; j <= j1; j++) {
                float dj = (float)(j - w);
                m = fminf(m, fmaf(dj, dj, exact_f2(n, c, h, j)));
            }
            if (m > 16.0f) {
                m = INFV;
                for (int j = 0; j < Ww; j++) {
                    float dj = (float)(j - w);
                    m = fminf(m, fmaf(dj, dj, exact_f2(n, c, h, j)));
                }
            }
            d[c] = sqrtf(m);
            e[c] = __expf(pred[n * CHW + c * HW + (h << 8) + w]);
        }
        float es = e[0] + e[1] + e[2] + e[3];
        num += (e[0] * d[0] + e[1] * d[1] + e[2] * d[2] + e[3] * d[3]) / es;
        den += d[0] + d[1] + d[2] + d[3];
    }
}

__device__ __forceinline__ float fsqrt_approx(float x) {
    float r;
    asm("sqrt.approx.f32 %0, %1;" : "=f"(r) : "f"(x));
    return r;
}

// ---------------------------------------------------------------------------
// Main pass. Block = 4 consecutive (n,h) rows, 256 threads, SINGLE WAVE
// (1024 blocks <= 148 SM x 7 resident via launch_bounds).
// P1: thread = (class, 4-px column); 10 unconditional LDG.64 from the padded
//     plane (guard rows are INF), register-rolled into 4 H-pass word-pairs.
// P2: thread = (row, 4-px); W window via PRMT half-shifts + softmax + reduce.
// Exactness: outside-window cost >= 16 in both H and W => any result <= 16
// is exact; any pixel whose true value > 16 trips the cold recompute.
__global__ void __launch_bounds__(256, 7) k_main(const float* __restrict__ pred,
                                                 float* __restrict__ out) {
    __shared__ unsigned int s_f2[4][4][132];  // [class][row][2 + 128 + 2] half2 words
    __shared__ float rnum[8], rden[8];
    __shared__ bool  s_last;

    const __half2 C1 = __float2half2_rn(1.0f);
    const __half2 C4 = __float2half2_rn(4.0f);
    const __half2 C9 = __float2half2_rn(9.0f);
    const unsigned int INFW = 0x5BF85BF8u;    // half2(255, 255)

    int tid = threadIdx.x;
    int n = blockIdx.x >> 6;
    int h0 = (blockIdx.x & 63) << 2;

    // s_f2 borders
    if (tid < 64) {
        int c = tid >> 4, r = (tid >> 2) & 3, b = tid & 3;
        s_f2[c][r][b < 2 ? b : 128 + b] = INFW;
    }

    // ---- P1: H-direction (native half2 min-plus, unconditional loads) ----
    {
        int c = tid >> 6, t = tid & 63;
        // row (h0-3+s) lives at padded row (h0+1+s)
        const __half* __restrict__ pc =
            g_f1h + (n * Cc + c) * PSTRIDE + ((h0 + 1) << 8) + (t << 2);
        uint2 v[10];
#pragma unroll
        for (int s = 0; s < 10; s++)
            v[s] = *(const uint2*)(pc + (s << 8));
#pragma unroll
        for (int r = 0; r < 4; r++) {
            __half2 aA = U2H(v[r + 3].x), aB = U2H(v[r + 3].y);
            aA = __hmin2(aA, __hadd2(__hmin2(U2H(v[r + 2].x), U2H(v[r + 4].x)), C1));
            aB = __hmin2(aB, __hadd2(__hmin2(U2H(v[r + 2].y), U2H(v[r + 4].y)), C1));
            aA = __hmin2(aA, __hadd2(__hmin2(U2H(v[r + 1].x), U2H(v[r + 5].x)), C4));
            aB = __hmin2(aB, __hadd2(__hmin2(U2H(v[r + 1].y), U2H(v[r + 5].y)), C4));
            aA = __hmin2(aA, __hadd2(__hmin2(U2H(v[r    ].x), U2H(v[r + 6].x)), C9));
            aB = __hmin2(aB, __hadd2(__hmin2(U2H(v[r    ].y), U2H(v[r + 6].y)), C9));
            *(uint2*)&s_f2[c][r][2 + 2 * t] = make_uint2(H2U(aA), H2U(aB));
        }
    }
    __syncthreads();

    // ---- P2: W-direction + softmax ----
    float num, den;
    {
        int row = tid >> 6, t = tid & 63;
        int h = h0 + row, w0 = t << 2;
        int pbase = n * CHW + (h << 8) + w0;

        float se[4]  = {0.f, 0.f, 0.f, 0.f};
        float sed[4] = {0.f, 0.f, 0.f, 0.f};
        den = 0.f;
        __half2 hmx = __float2half2_rn(0.0f);

#pragma unroll
        for (int c = 0; c < 4; c++) {
            const unsigned int* __restrict__ sb = s_f2[c][row];
            uint2 wa = *(const uint2*)(sb + 2 * t);      // logical words 2t-2, 2t-1
            uint2 wb = *(const uint2*)(sb + 2 * t + 2);  // 2t, 2t+1 (center)
            uint2 wc = *(const uint2*)(sb + 2 * t + 4);  // 2t+2, 2t+3

            unsigned int p01 = __byte_perm(wa.x, wa.y, 0x5432);
            unsigned int p12 = __byte_perm(wa.y, wb.x, 0x5432);
            unsigned int p23 = __byte_perm(wb.x, wb.y, 0x5432);
            unsigned int p34 = __byte_perm(wb.y, wc.x, 0x5432);
            unsigned int p45 = __byte_perm(wc.x, wc.y, 0x5432);

            __half2 aA = U2H(wb.x), aB = U2H(wb.y);
            aA = __hmin2(aA, __hadd2(__hmin2(U2H(p12), U2H(p23)), C1));
            aB = __hmin2(aB, __hadd2(__hmin2(U2H(p23), U2H(p34)), C1));
            aA = __hmin2(aA, __hadd2(__hmin2(U2H(wa.y), U2H(wb.y)), C4));
            aB = __hmin2(aB, __hadd2(__hmin2(U2H(wb.x), U2H(wc.x)), C4));
            aA = __hmin2(aA, __hadd2(__hmin2(U2H(p01), U2H(p34)), C9));
            aB = __hmin2(aB, __hadd2(__hmin2(U2H(p12), U2H(p45)), C9));
            hmx = __hmax2(hmx, __hmax2(aA, aB));

            float2 fA = __half22float2(aA), fB = __half22float2(aB);
            float d0 = fsqrt_approx(fA.x), d1 = fsqrt_approx(fA.y);
            float d2 = fsqrt_approx(fB.x), d3 = fsqrt_approx(fB.y);

            float4 x4 = *(const float4*)(pred + pbase + c * HW);
            float e0 = __expf(x4.x), e1 = __expf(x4.y), e2 = __expf(x4.z), e3 = __expf(x4.w);
            se[0]  += e0;      se[1]  += e1;      se[2]  += e2;      se[3]  += e3;
            sed[0] += e0 * d0; sed[1] += e1 * d1; sed[2] += e2 * d2; sed[3] += e3 * d3;
            den += (d0 + d1) + (d2 + d3);
        }

        num = __fdividef(sed[0], se[0]) + __fdividef(sed[1], se[1]) +
              __fdividef(sed[2], se[2]) + __fdividef(sed[3], se[3]);

        float chk = fmaxf(__half2float(__low2half(hmx)), __half2float(__high2half(hmx)));
        if (chk > 16.0f)     // astronomically cold: redo this unit exactly
            recompute_unit(n, h, w0, pred, num, den);
    }

    // ---- block reduce ----
#pragma unroll
    for (int o = 16; o; o >>= 1) {
        num += __shfl_xor_sync(0xFFFFFFFFu, num, o);
        den += __shfl_xor_sync(0xFFFFFFFFu, den, o);
    }
    int lane = tid & 31, wid = tid >> 5;
    if (lane == 0) { rnum[wid] = num; rden[wid] = den; }
    __syncthreads();
    if (wid == 0) {
        num = (lane < 8) ? rnum[lane] : 0.f;
        den = (lane < 8) ? rden[lane] : 0.f;
#pragma unroll
        for (int o = 4; o; o >>= 1) {
            num += __shfl_xor_sync(0xFFFFFFFFu, num, o);
            den += __shfl_xor_sync(0xFFFFFFFFu, den, o);
        }
        if (lane == 0) g_part[blockIdx.x] = make_float2(num, den);
    }

    // ---- last-block final reduction (self-resetting counter) ----
    __threadfence();
    if (threadIdx.x == 0) {
        unsigned int prevc = atomicInc(&g_ctr, NBLK - 1);  // wraps to 0 on last
        s_last = (prevc == (unsigned int)(NBLK - 1));
    }
    __syncthreads();
    if (!s_last) return;

    __shared__ double snum[8], sden[8];
    double dn = 0.0, dd = 0.0;
#pragma unroll
    for (int q = 0; q < NBLK / 256; q++) {
        float2 p = g_part[q * 256 + tid];
        dn += (double)p.x;
        dd += (double)p.y;
    }
#pragma unroll
    for (int o = 16; o; o >>= 1) {
        dn += __shfl_xor_sync(0xFFFFFFFFu, dn, o);
        dd += __shfl_xor_sync(0xFFFFFFFFu, dd, o);
    }
    if (lane == 0) { snum[wid] = dn; sden[wid] = dd; }
    __syncthreads();
    if (wid == 0) {
        dn = (lane < 8) ? snum[lane] : 0.0;
        dd = (lane < 8) ? sden[lane] : 0.0;
#pragma unroll
        for (int o = 4; o; o >>= 1) {
            dn += __shfl_xor_sync(0xFFFFFFFFu, dn, o);
            dd += __shfl_xor_sync(0xFFFFFFFFu, dd, o);
        }
        if (lane == 0) out[0] = (float)(dn / (dd + 1e-10));
    }
}

// ---------------------------------------------------------------------------
extern "C" void kernel_launch(void* const* d_in, const int* in_sizes, int n_in,
                              void* d_out, int out_size) {
    const float* pred = (const float*)d_in[0];
    const int*   tgt  = (const int*)d_in[1];
    float*       out  = (float*)d_out;

    k_cpass<<<(Nn * HW / 8) / 256, 256>>>(tgt);
    k_main<<<NBLK, 256>>>(pred, out);
}